// round 5
// baseline (speedup 1.0000x reference)
#include <cuda_runtime.h>
#include <math.h>

#define Bn 4
#define Sn 4096
#define Dn 256
#define Mrows (Bn*Sn)   // 16384

// -------- scratch (device globals; allocation-free rule) --------
// NOTE: __align__(16) is load-bearing — these are accessed as float4/uint4,
// and __device__ arrays only get their element type's alignment by default.
__device__ __align__(16) float    g_vp [(size_t)Mrows * Dn];   // v-projection
__device__ __align__(16) float    g_pre[(size_t)Mrows * Dn];   // attn^T@vp, then tanh'd
__device__ __align__(16) unsigned g_sqbits[Mrows * 8];         // sign bits of q-proj
__device__ __align__(16) unsigned g_skbits[Mrows * 8];         // sign bits of k-proj
__device__ __align__(16) float    g_rowsum[Mrows];             // softmax denominators

// ============================================================
// GEMM: C[M,256] = A[M,256] @ W[256,256] + bias
// signMode=1: emit sign bits (atomicOr, idempotent) instead of floats
// tile 64x64, BK=16, 256 threads, 4x4 per thread
// ============================================================
__global__ __launch_bounds__(256) void gemm256(
    const float* __restrict__ A, const float* __restrict__ W,
    const float* __restrict__ bias, float* __restrict__ outF,
    unsigned* __restrict__ outBits, int signMode)
{
    __shared__ __align__(16) float As[16][64];   // transposed: As[k][m]
    __shared__ __align__(16) float Ws[16][64];
    const int t  = threadIdx.x;
    const int m0 = blockIdx.y * 64;
    const int n0 = blockIdx.x * 64;
    const int tm = t >> 4, tn = t & 15;
    const int ar = t >> 2, ac4 = (t & 3) << 2;     // A tile load: 64 rows x 16 k
    const int wr = t >> 4, wc4 = (t & 15) << 2;    // W tile load: 16 k x 64 n

    float acc[4][4] = {};

    for (int k0 = 0; k0 < Dn; k0 += 16) {
        float4 av = *(const float4*)&A[(size_t)(m0 + ar) * Dn + k0 + ac4];
        float4 wv = *(const float4*)&W[(size_t)(k0 + wr) * Dn + n0 + wc4];
        __syncthreads();
        As[ac4 + 0][ar] = av.x; As[ac4 + 1][ar] = av.y;
        As[ac4 + 2][ar] = av.z; As[ac4 + 3][ar] = av.w;
        *(float4*)&Ws[wr][wc4] = wv;
        __syncthreads();
        #pragma unroll
        for (int kk = 0; kk < 16; kk++) {
            float4 a4 = *(const float4*)&As[kk][tm << 2];
            float4 w4 = *(const float4*)&Ws[kk][tn << 2];
            acc[0][0] = fmaf(a4.x, w4.x, acc[0][0]);
            acc[0][1] = fmaf(a4.x, w4.y, acc[0][1]);
            acc[0][2] = fmaf(a4.x, w4.z, acc[0][2]);
            acc[0][3] = fmaf(a4.x, w4.w, acc[0][3]);
            acc[1][0] = fmaf(a4.y, w4.x, acc[1][0]);
            acc[1][1] = fmaf(a4.y, w4.y, acc[1][1]);
            acc[1][2] = fmaf(a4.y, w4.z, acc[1][2]);
            acc[1][3] = fmaf(a4.y, w4.w, acc[1][3]);
            acc[2][0] = fmaf(a4.z, w4.x, acc[2][0]);
            acc[2][1] = fmaf(a4.z, w4.y, acc[2][1]);
            acc[2][2] = fmaf(a4.z, w4.z, acc[2][2]);
            acc[2][3] = fmaf(a4.z, w4.w, acc[2][3]);
            acc[3][0] = fmaf(a4.w, w4.x, acc[3][0]);
            acc[3][1] = fmaf(a4.w, w4.y, acc[3][1]);
            acc[3][2] = fmaf(a4.w, w4.z, acc[3][2]);
            acc[3][3] = fmaf(a4.w, w4.w, acc[3][3]);
        }
    }

    float4 bv = *(const float4*)&bias[n0 + (tn << 2)];
    #pragma unroll
    for (int i = 0; i < 4; i++) {
        const int row = m0 + (tm << 2) + i;
        float4 c = make_float4(acc[i][0] + bv.x, acc[i][1] + bv.y,
                               acc[i][2] + bv.z, acc[i][3] + bv.w);
        if (!signMode) {
            *(float4*)&outF[(size_t)row * Dn + n0 + (tn << 2)] = c;
        } else {
            const int colb = tn << 2;            // 4-aligned -> all 4 bits in one word
            unsigned bm = 0;
            if (c.x < 0.f) bm |= 1u << ((colb + 0) & 31);
            if (c.y < 0.f) bm |= 1u << ((colb + 1) & 31);
            if (c.z < 0.f) bm |= 1u << ((colb + 2) & 31);
            if (c.w < 0.f) bm |= 1u << ((colb + 3) & 31);
            if (bm) atomicOr(&outBits[row * 8 + ((n0 + colb) >> 5)], bm);
        }
    }
}

// ============================================================
// rowsum[b,k] = sum_q exp((256 - popc(skbits[k]^sqbits[q]))/512)
// CTA: 256 threads, 64 k-rows, 4 q-slices per row; q staged in smem
// ============================================================
__global__ __launch_bounds__(256) void rowsum_kernel()
{
    __shared__ float table[257];
    __shared__ __align__(16) uint4 qbf[1024];      // 512 q-rows * 8 u32
    __shared__ float red[64][4];
    const int t  = threadIdx.x;
    const int b  = blockIdx.y;
    const int k0 = blockIdx.x * 64;

    for (int i = t; i < 257; i += 256) table[i] = expf((256.0f - i) * (1.0f / 512.0f));

    const int kr = t >> 2, part = t & 3;
    const uint4* kb = (const uint4*)&g_skbits[((size_t)b * Sn + k0 + kr) * 8];
    const uint4 k0v = kb[0], k1v = kb[1];
    float sum = 0.f;

    for (int q0 = 0; q0 < Sn; q0 += 512) {
        const uint4* src = (const uint4*)&g_sqbits[((size_t)b * Sn + q0) * 8];
        __syncthreads();
        #pragma unroll
        for (int i = 0; i < 4; i++) qbf[t + 256 * i] = src[t + 256 * i];
        __syncthreads();
        for (int q = part; q < 512; q += 4) {
            uint4 a = qbf[q * 2], c = qbf[q * 2 + 1];
            int pc = __popc(a.x ^ k0v.x) + __popc(a.y ^ k0v.y)
                   + __popc(a.z ^ k0v.z) + __popc(a.w ^ k0v.w)
                   + __popc(c.x ^ k1v.x) + __popc(c.y ^ k1v.y)
                   + __popc(c.z ^ k1v.z) + __popc(c.w ^ k1v.w);
            sum += table[pc];
        }
    }
    red[kr][part] = sum;
    __syncthreads();
    if (t < 64)
        g_rowsum[(size_t)b * Sn + k0 + t] =
            (red[t][0] + red[t][1]) + (red[t][2] + red[t][3]);
}

// ============================================================
// Fused: attn[b,k,q] = exp_lut/rowsum[k] * mask[b,k,q]  (written to d_out)
//        g_pre[b,q,d] = sum_k attn[b,k,q] * vp[b,k,d]
// CTA = (64-q tile, batch); full D=256; K chunks of 16.
// 256 threads, 4q x 16d accumulators per thread (64 fp32 regs).
// ============================================================
#define FMA4(C,S,V) { C.x = fmaf(S, V.x, C.x); C.y = fmaf(S, V.y, C.y); \
                      C.z = fmaf(S, V.z, C.z); C.w = fmaf(S, V.w, C.w); }

__global__ __launch_bounds__(256, 2) void attn_out_kernel(
    const float* __restrict__ mask, float* __restrict__ attn_out)
{
    __shared__ float    table[257];
    __shared__ __align__(16) unsigned sqb[64][8];
    __shared__ __align__(16) unsigned skb[16][8];
    __shared__ float    inv_rs[16];
    __shared__ __align__(16) float    vps[16][256];
    __shared__ __align__(16) float    ats[16][64];
    __shared__ __align__(16) float    msk[16][64];

    const int t  = threadIdx.x;
    const int b  = blockIdx.y;
    const int q0 = blockIdx.x * 64;

    for (int i = t; i < 257; i += 256) table[i] = expf((256.0f - i) * (1.0f / 512.0f));
    {
        const unsigned* src = &g_sqbits[((size_t)b * Sn + q0) * 8];
        ((unsigned*)sqb)[t]       = src[t];
        ((unsigned*)sqb)[t + 256] = src[t + 256];
    }

    const int qg = t >> 4, dg = t & 15;
    float4 acc[4][4];
    #pragma unroll
    for (int i = 0; i < 4; i++)
        #pragma unroll
        for (int j = 0; j < 4; j++) acc[i][j] = make_float4(0.f, 0.f, 0.f, 0.f);
    __syncthreads();

    for (int k0 = 0; k0 < Sn; k0 += 16) {
        // ---- stage vp / mask / k-bits / 1/rowsum ----
        const float4* vg = (const float4*)&g_vp[((size_t)b * Sn + k0) * Dn];
        #pragma unroll
        for (int i = 0; i < 4; i++) ((float4*)vps)[t + 256 * i] = vg[t + 256 * i];
        {
            const int r = t >> 4, c4 = (t & 15) << 2;
            *(float4*)&msk[r][c4] =
                *(const float4*)&mask[((size_t)b * Sn + k0 + r) * Sn + q0 + c4];
        }
        if (t < 128) ((unsigned*)skb)[t] = g_skbits[((size_t)b * Sn + k0) * 8 + t];
        if (t < 16)  inv_rs[t] = 1.0f / g_rowsum[(size_t)b * Sn + k0 + t];
        __syncthreads();

        // ---- attn tile (16k x 64q) via XOR/POPC + LUT; write to output ----
        #pragma unroll
        for (int j = 0; j < 4; j++) {
            const int idx = t + 256 * j;
            const int kk = idx >> 6, qq = idx & 63;
            int pc = 0;
            #pragma unroll
            for (int w = 0; w < 8; w++) pc += __popc(skb[kk][w] ^ sqb[qq][w]);
            const float a = table[pc] * inv_rs[kk] * msk[kk][qq];
            ats[kk][qq] = a;
            attn_out[((size_t)b * Sn + k0 + kk) * Sn + q0 + qq] = a;
        }
        __syncthreads();

        // ---- micro-GEMM: acc[q,d] += attn[k,q] * vp[k,d] ----
        #pragma unroll 4
        for (int kk = 0; kk < 16; kk++) {
            float4 aq = *(const float4*)&ats[kk][qg << 2];
            const float4* vr = (const float4*)&vps[kk][dg << 4];
            float4 v0 = vr[0], v1 = vr[1], v2 = vr[2], v3 = vr[3];
            FMA4(acc[0][0], aq.x, v0); FMA4(acc[0][1], aq.x, v1);
            FMA4(acc[0][2], aq.x, v2); FMA4(acc[0][3], aq.x, v3);
            FMA4(acc[1][0], aq.y, v0); FMA4(acc[1][1], aq.y, v1);
            FMA4(acc[1][2], aq.y, v2); FMA4(acc[1][3], aq.y, v3);
            FMA4(acc[2][0], aq.z, v0); FMA4(acc[2][1], aq.z, v1);
            FMA4(acc[2][2], aq.z, v2); FMA4(acc[2][3], aq.z, v3);
            FMA4(acc[3][0], aq.w, v0); FMA4(acc[3][1], aq.w, v1);
            FMA4(acc[3][2], aq.w, v2); FMA4(acc[3][3], aq.w, v3);
        }
        __syncthreads();
    }

    #pragma unroll
    for (int i = 0; i < 4; i++) {
        float* dst = &g_pre[((size_t)b * Sn + q0 + (qg << 2) + i) * Dn + (dg << 4)];
        ((float4*)dst)[0] = acc[i][0];
        ((float4*)dst)[1] = acc[i][1];
        ((float4*)dst)[2] = acc[i][2];
        ((float4*)dst)[3] = acc[i][3];
    }
}

// ============================================================
// in-place: g_pre = tanh(g_pre * anchor)  (anchor broadcast over batch)
// ============================================================
__global__ void tanh_anchor_kernel(const float* __restrict__ anchor)
{
    const size_t i = (size_t)blockIdx.x * blockDim.x + threadIdx.x;
    g_pre[i] = tanhf(g_pre[i] * anchor[i & (size_t)(Sn * Dn - 1)]);
}

// ============================================================
extern "C" void kernel_launch(void* const* d_in, const int* in_sizes, int n_in,
                              void* d_out, int out_size)
{
    const float* v       = (const float*)d_in[0];
    const float* k       = (const float*)d_in[1];
    const float* q       = (const float*)d_in[2];
    const float* mask    = (const float*)d_in[3];
    const float* wq_k    = (const float*)d_in[4];
    const float* wq_b    = (const float*)d_in[5];
    const float* wk_k    = (const float*)d_in[6];
    const float* wk_b    = (const float*)d_in[7];
    const float* wv_k    = (const float*)d_in[8];
    const float* wv_b    = (const float*)d_in[9];
    const float* anchor  = (const float*)d_in[10];
    const float* dense_k = (const float*)d_in[11];
    const float* dense_b = (const float*)d_in[12];

    float* out  = (float*)d_out;                      // [B,S,D]
    float* attn = out + (size_t)Mrows * Dn;           // [B,S,S]

    void *p_vp, *p_pre, *p_sq, *p_sk;
    cudaGetSymbolAddress(&p_vp,  g_vp);
    cudaGetSymbolAddress(&p_pre, g_pre);
    cudaGetSymbolAddress(&p_sq,  g_sqbits);
    cudaGetSymbolAddress(&p_sk,  g_skbits);

    dim3 gg(Dn / 64, Mrows / 64), tb(256);
    gemm256<<<gg, tb>>>(q, wq_k, wq_b, nullptr, (unsigned*)p_sq, 1);
    gemm256<<<gg, tb>>>(k, wk_k, wk_b, nullptr, (unsigned*)p_sk, 1);
    gemm256<<<gg, tb>>>(v, wv_k, wv_b, (float*)p_vp, nullptr, 0);

    rowsum_kernel<<<dim3(Sn / 64, Bn), 256>>>();
    attn_out_kernel<<<dim3(Sn / 64, Bn), 256>>>(mask, attn);

    tanh_anchor_kernel<<<(Mrows * Dn) / 1024, 1024>>>(anchor);
    gemm256<<<gg, tb>>>((const float*)p_pre, dense_k, dense_b, out, nullptr, 0);
}

// round 8
// speedup vs baseline: 6.5145x; 6.5145x over previous
#include <cuda_runtime.h>
#include <cuda_fp16.h>
#include <math.h>

#define Bn 4
#define Sn 4096
#define Dn 256
#define Mrows (Bn*Sn)   // 16384

// -------- scratch (device globals; allocation-free rule) --------
__device__ __align__(16) __half   g_vph[(size_t)Mrows * Dn];   // v-projection, fp16
__device__ __align__(16) float    g_pre[(size_t)Mrows * Dn];   // attn^T@vp, then tanh'd
__device__ __align__(16) unsigned g_sqbits[Mrows * 8];         // sign bits of q-proj
__device__ __align__(16) unsigned g_skbits[Mrows * 8];         // sign bits of k-proj
__device__ __align__(16) float    g_rowsum4[4][Mrows];         // partial softmax denominators

__device__ __forceinline__ unsigned s2u(const void* p) {
    return (unsigned)__cvta_generic_to_shared(p);
}

// ============================================================
// GEMM: C[M,256] = A[M,256] @ W[256,256] + bias
// mode 0: fp32 out; mode 1: sign bits (atomicOr, idempotent); mode 2: fp16 out
// tile 64x64, BK=16, 256 threads, 4x4 per thread
// ============================================================
__global__ __launch_bounds__(256) void gemm256(
    const float* __restrict__ A, const float* __restrict__ W,
    const float* __restrict__ bias, float* __restrict__ outF,
    unsigned* __restrict__ outBits, __half* __restrict__ outH, int mode)
{
    __shared__ __align__(16) float As[16][64];   // transposed: As[k][m]
    __shared__ __align__(16) float Ws[16][64];
    const int t  = threadIdx.x;
    const int m0 = blockIdx.y * 64;
    const int n0 = blockIdx.x * 64;
    const int tm = t >> 4, tn = t & 15;
    const int ar = t >> 2, ac4 = (t & 3) << 2;
    const int wr = t >> 4, wc4 = (t & 15) << 2;

    float acc[4][4] = {};

    for (int k0 = 0; k0 < Dn; k0 += 16) {
        float4 av = *(const float4*)&A[(size_t)(m0 + ar) * Dn + k0 + ac4];
        float4 wv = *(const float4*)&W[(size_t)(k0 + wr) * Dn + n0 + wc4];
        __syncthreads();
        As[ac4 + 0][ar] = av.x; As[ac4 + 1][ar] = av.y;
        As[ac4 + 2][ar] = av.z; As[ac4 + 3][ar] = av.w;
        *(float4*)&Ws[wr][wc4] = wv;
        __syncthreads();
        #pragma unroll
        for (int kk = 0; kk < 16; kk++) {
            float4 a4 = *(const float4*)&As[kk][tm << 2];
            float4 w4 = *(const float4*)&Ws[kk][tn << 2];
            acc[0][0] = fmaf(a4.x, w4.x, acc[0][0]);
            acc[0][1] = fmaf(a4.x, w4.y, acc[0][1]);
            acc[0][2] = fmaf(a4.x, w4.z, acc[0][2]);
            acc[0][3] = fmaf(a4.x, w4.w, acc[0][3]);
            acc[1][0] = fmaf(a4.y, w4.x, acc[1][0]);
            acc[1][1] = fmaf(a4.y, w4.y, acc[1][1]);
            acc[1][2] = fmaf(a4.y, w4.z, acc[1][2]);
            acc[1][3] = fmaf(a4.y, w4.w, acc[1][3]);
            acc[2][0] = fmaf(a4.z, w4.x, acc[2][0]);
            acc[2][1] = fmaf(a4.z, w4.y, acc[2][1]);
            acc[2][2] = fmaf(a4.z, w4.z, acc[2][2]);
            acc[2][3] = fmaf(a4.z, w4.w, acc[2][3]);
            acc[3][0] = fmaf(a4.w, w4.x, acc[3][0]);
            acc[3][1] = fmaf(a4.w, w4.y, acc[3][1]);
            acc[3][2] = fmaf(a4.w, w4.z, acc[3][2]);
            acc[3][3] = fmaf(a4.w, w4.w, acc[3][3]);
        }
    }

    float4 bv = *(const float4*)&bias[n0 + (tn << 2)];
    #pragma unroll
    for (int i = 0; i < 4; i++) {
        const int row = m0 + (tm << 2) + i;
        float4 c = make_float4(acc[i][0] + bv.x, acc[i][1] + bv.y,
                               acc[i][2] + bv.z, acc[i][3] + bv.w);
        if (mode == 0) {
            *(float4*)&outF[(size_t)row * Dn + n0 + (tn << 2)] = c;
        } else if (mode == 1) {
            const int colb = tn << 2;
            unsigned bm = 0;
            if (c.x < 0.f) bm |= 1u << ((colb + 0) & 31);
            if (c.y < 0.f) bm |= 1u << ((colb + 1) & 31);
            if (c.z < 0.f) bm |= 1u << ((colb + 2) & 31);
            if (c.w < 0.f) bm |= 1u << ((colb + 3) & 31);
            if (bm) atomicOr(&outBits[row * 8 + ((n0 + colb) >> 5)], bm);
        } else {
            unsigned u0, u1;
            asm("cvt.rn.f16x2.f32 %0, %1, %2;" : "=r"(u0) : "f"(c.y), "f"(c.x));
            asm("cvt.rn.f16x2.f32 %0, %1, %2;" : "=r"(u1) : "f"(c.w), "f"(c.z));
            *(uint2*)&outH[(size_t)row * Dn + n0 + (tn << 2)] = make_uint2(u0, u1);
        }
    }
}

// ============================================================
// g_rowsum4[qsel][b,k] = sum_{q in qsel-quarter} exp((256-popc)/512)
// grid (256, Bn): blockIdx.x = ktile*4 + qsel ; 64 k-rows per CTA
// ============================================================
__global__ __launch_bounds__(256) void rowsum_kernel()
{
    __shared__ float table[257];
    __shared__ __align__(16) uint4 qbf[1024];      // 512 q-rows * 8 u32
    __shared__ float red[64][4];
    const int t    = threadIdx.x;
    const int b    = blockIdx.y;
    const int k0   = (blockIdx.x >> 2) * 64;
    const int qsel = blockIdx.x & 3;

    for (int i = t; i < 257; i += 256) table[i] = expf((256.0f - i) * (1.0f / 512.0f));

    const int kr = t >> 2, part = t & 3;
    const uint4* kb = (const uint4*)&g_skbits[((size_t)b * Sn + k0 + kr) * 8];
    const uint4 k0v = kb[0], k1v = kb[1];
    float sum = 0.f;

    for (int q0 = qsel * 1024; q0 < qsel * 1024 + 1024; q0 += 512) {
        const uint4* src = (const uint4*)&g_sqbits[((size_t)b * Sn + q0) * 8];
        __syncthreads();
        #pragma unroll
        for (int i = 0; i < 4; i++) qbf[t + 256 * i] = src[t + 256 * i];
        __syncthreads();
        for (int q = part; q < 512; q += 4) {
            uint4 a = qbf[q * 2], c = qbf[q * 2 + 1];
            int pc = __popc(a.x ^ k0v.x) + __popc(a.y ^ k0v.y)
                   + __popc(a.z ^ k0v.z) + __popc(a.w ^ k0v.w)
                   + __popc(c.x ^ k1v.x) + __popc(c.y ^ k1v.y)
                   + __popc(c.z ^ k1v.z) + __popc(c.w ^ k1v.w);
            sum += table[pc];
        }
    }
    red[kr][part] = sum;
    __syncthreads();
    if (t < 64)
        g_rowsum4[qsel][(size_t)b * Sn + k0 + t] =
            (red[t][0] + red[t][1]) + (red[t][2] + red[t][3]);
}

// ============================================================
// Fused: attn[b,k,q] (fp32 -> d_out) + out_pre[b,q,d] via mma.sync fp16
// CTA = (64-q tile, batch); K chunks of 32; 8 warps = 2q x 4d.
// ============================================================
#define LDMX4(r0,r1,r2,r3,addr) \
    asm volatile("ldmatrix.sync.aligned.m8n8.x4.shared.b16 {%0,%1,%2,%3}, [%4];" \
        : "=r"(r0),"=r"(r1),"=r"(r2),"=r"(r3) : "r"(addr))
#define LDMX4T(r0,r1,r2,r3,addr) \
    asm volatile("ldmatrix.sync.aligned.m8n8.x4.trans.shared.b16 {%0,%1,%2,%3}, [%4];" \
        : "=r"(r0),"=r"(r1),"=r"(r2),"=r"(r3) : "r"(addr))
#define MMA16816(C,A0,A1,A2,A3,B0,B1) \
    asm volatile("mma.sync.aligned.m16n8k16.row.col.f32.f16.f16.f32 " \
        "{%0,%1,%2,%3}, {%4,%5,%6,%7}, {%8,%9}, {%0,%1,%2,%3};" \
        : "+f"(C[0]),"+f"(C[1]),"+f"(C[2]),"+f"(C[3]) \
        : "r"(A0),"r"(A1),"r"(A2),"r"(A3), "r"(B0),"r"(B1))

#define LDD 264   // vp_s row pitch in halfs (256 + 8)
#define LDK 40    // ats  row pitch in halfs (32 + 8)

__global__ __launch_bounds__(256, 2) void attn_mma_kernel(
    const float* __restrict__ mask, float* __restrict__ attn_out)
{
    __shared__ __align__(16) __half   vp_s[2][32][LDD];  // 33792 B (double-buffered)
    __shared__ __align__(16) __half   ats[64][LDK];      //  5120 B
    __shared__ __align__(16) float    msk[32][64];       //  8192 B
    __shared__ __align__(16) unsigned skb[32][8];        //  1024 B
    __shared__ float inv_rs[32];                         //   128 B  (total 48256 B)

    const int t    = threadIdx.x;
    const int b    = blockIdx.y;
    const int q0   = blockIdx.x * 64;
    const int lane = t & 31, wid = t >> 5;
    const int wq   = wid >> 2, wd = wid & 3;
    const int qq   = t & 63;

    // q sign bits: register-resident for the whole kernel
    const uint4* sqp = (const uint4*)&g_sqbits[((size_t)b * Sn + q0 + qq) * 8];
    const uint4 sq0 = sqp[0], sq1 = sqp[1];

    float acc[2][8][4];
    #pragma unroll
    for (int m = 0; m < 2; m++)
        #pragma unroll
        for (int n = 0; n < 8; n++)
            #pragma unroll
            for (int j = 0; j < 4; j++) acc[m][n][j] = 0.f;

    // ---- prefetch registers ----
    uint4  vpr[4];   // 64 halfs of vp tile
    float4 mkr[2];   // 8 floats of mask tile
    uint4  skr;      // k sign bits (t<64)
    float  invr = 0.f;

    // prefetch tile 0
    {
        const uint4* vg = (const uint4*)&g_vph[((size_t)b * Sn) * Dn];
        #pragma unroll
        for (int i = 0; i < 4; i++) vpr[i] = vg[t + 256 * i];
        #pragma unroll
        for (int i = 0; i < 2; i++) {
            const int u = t + 256 * i, kk = u >> 4, q4 = (u & 15) << 2;
            mkr[i] = *(const float4*)&mask[((size_t)b * Sn + kk) * Sn + q0 + q4];
        }
        if (t < 64) skr = ((const uint4*)&g_skbits[((size_t)b * Sn) * 8])[t];
        if (t < 32) {
            const size_t r = (size_t)b * Sn + t;
            invr = 1.0f / (g_rowsum4[0][r] + g_rowsum4[1][r] + g_rowsum4[2][r] + g_rowsum4[3][r]);
        }
    }

    const unsigned ats_base = s2u(&ats[0][0]);

    for (int it = 0; it < Sn / 32; it++) {
        const int cur = it & 1;
        // ---- commit staged regs to smem ----
        #pragma unroll
        for (int i = 0; i < 4; i++) {
            const int u = t + 256 * i;
            *(uint4*)&vp_s[cur][u >> 5][(u & 31) << 3] = vpr[i];
        }
        #pragma unroll
        for (int i = 0; i < 2; i++) {
            const int u = t + 256 * i;
            *(float4*)&msk[u >> 4][(u & 15) << 2] = mkr[i];
        }
        if (t < 64) ((uint4*)skb)[t] = skr;
        if (t < 32) inv_rs[t] = invr;

        // ---- prefetch next tile ----
        if (it + 1 < Sn / 32) {
            const int k0n = (it + 1) * 32;
            const uint4* vg = (const uint4*)&g_vph[((size_t)b * Sn + k0n) * Dn];
            #pragma unroll
            for (int i = 0; i < 4; i++) vpr[i] = vg[t + 256 * i];
            #pragma unroll
            for (int i = 0; i < 2; i++) {
                const int u = t + 256 * i, kk = u >> 4, q4 = (u & 15) << 2;
                mkr[i] = *(const float4*)&mask[((size_t)b * Sn + k0n + kk) * Sn + q0 + q4];
            }
            if (t < 64) skr = ((const uint4*)&g_skbits[((size_t)b * Sn + k0n) * 8])[t];
            if (t < 32) {
                const size_t r = (size_t)b * Sn + k0n + t;
                invr = 1.0f / (g_rowsum4[0][r] + g_rowsum4[1][r] + g_rowsum4[2][r] + g_rowsum4[3][r]);
            }
        }
        __syncthreads();

        // ---- attn tile (32k x 64q): popc + __expf; STG fp32 + STS fp16 ----
        #pragma unroll
        for (int r = 0; r < 4; r++) {
            const int kk = ((t >> 6) << 1) + (r << 3);   // even, pairs {kk, kk+1}
            float a2[2];
            #pragma unroll
            for (int j = 0; j < 2; j++) {
                const unsigned* sk = skb[kk + j];
                int pc = __popc(sk[0] ^ sq0.x) + __popc(sk[1] ^ sq0.y)
                       + __popc(sk[2] ^ sq0.z) + __popc(sk[3] ^ sq0.w)
                       + __popc(sk[4] ^ sq1.x) + __popc(sk[5] ^ sq1.y)
                       + __popc(sk[6] ^ sq1.z) + __popc(sk[7] ^ sq1.w);
                const float a = __expf((float)(256 - pc) * (1.0f / 512.0f))
                              * inv_rs[kk + j] * msk[kk + j][qq];
                a2[j] = a;
                attn_out[((size_t)b * Sn + it * 32 + kk + j) * Sn + q0 + qq] = a;
            }
            unsigned p;
            asm("cvt.rn.f16x2.f32 %0, %1, %2;" : "=r"(p) : "f"(a2[1]), "f"(a2[0]));
            *(unsigned*)&ats[qq][kk] = p;
        }
        __syncthreads();

        // ---- tensor-core micro-GEMM: acc[q,d] += ats[q,k] * vp[k,d] ----
        const unsigned vp_base = s2u(&vp_s[cur][0][0]);
        #pragma unroll
        for (int kt = 0; kt < 2; kt++) {
            unsigned a0[4], a1[4];
            const unsigned acol = (kt * 16 + (lane >> 4) * 8) * 2;
            LDMX4(a0[0], a0[1], a0[2], a0[3],
                  ats_base + (wq * 32 + (lane & 15)) * (LDK * 2) + acol);
            LDMX4(a1[0], a1[1], a1[2], a1[3],
                  ats_base + (wq * 32 + 16 + (lane & 15)) * (LDK * 2) + acol);
            #pragma unroll
            for (int np = 0; np < 4; np++) {
                unsigned bf[4];
                LDMX4T(bf[0], bf[1], bf[2], bf[3],
                       vp_base + (kt * 16 + (lane & 15)) * (LDD * 2)
                               + (wd * 64 + np * 16 + (lane >> 4) * 8) * 2);
                MMA16816(acc[0][np * 2 + 0], a0[0], a0[1], a0[2], a0[3], bf[0], bf[1]);
                MMA16816(acc[0][np * 2 + 1], a0[0], a0[1], a0[2], a0[3], bf[2], bf[3]);
                MMA16816(acc[1][np * 2 + 0], a1[0], a1[1], a1[2], a1[3], bf[0], bf[1]);
                MMA16816(acc[1][np * 2 + 1], a1[0], a1[1], a1[2], a1[3], bf[2], bf[3]);
            }
        }
    }

    // ---- epilogue: fragment -> g_pre (fp32) ----
    #pragma unroll
    for (int m = 0; m < 2; m++) {
        const int q = q0 + wq * 32 + m * 16 + (lane >> 2);
        #pragma unroll
        for (int n = 0; n < 8; n++) {
            const int d = wd * 64 + n * 8 + ((lane & 3) << 1);
            *(float2*)&g_pre[((size_t)b * Sn + q) * Dn + d] =
                make_float2(acc[m][n][0], acc[m][n][1]);
            *(float2*)&g_pre[((size_t)b * Sn + q + 8) * Dn + d] =
                make_float2(acc[m][n][2], acc[m][n][3]);
        }
    }
}

// ============================================================
// in-place: g_pre = tanh(g_pre * anchor)  (anchor broadcast over batch)
// ============================================================
__global__ void tanh_anchor_kernel(const float* __restrict__ anchor)
{
    const size_t i = (size_t)blockIdx.x * blockDim.x + threadIdx.x;
    g_pre[i] = tanhf(g_pre[i] * anchor[i & (size_t)(Sn * Dn - 1)]);
}

// ============================================================
extern "C" void kernel_launch(void* const* d_in, const int* in_sizes, int n_in,
                              void* d_out, int out_size)
{
    const float* v       = (const float*)d_in[0];
    const float* k       = (const float*)d_in[1];
    const float* q       = (const float*)d_in[2];
    const float* mask    = (const float*)d_in[3];
    const float* wq_k    = (const float*)d_in[4];
    const float* wq_b    = (const float*)d_in[5];
    const float* wk_k    = (const float*)d_in[6];
    const float* wk_b    = (const float*)d_in[7];
    const float* wv_k    = (const float*)d_in[8];
    const float* wv_b    = (const float*)d_in[9];
    const float* anchor  = (const float*)d_in[10];
    const float* dense_k = (const float*)d_in[11];
    const float* dense_b = (const float*)d_in[12];

    float* out  = (float*)d_out;                      // [B,S,D]
    float* attn = out + (size_t)Mrows * Dn;           // [B,S,S]

    void *p_vph, *p_pre, *p_sq, *p_sk;
    cudaGetSymbolAddress(&p_vph, g_vph);
    cudaGetSymbolAddress(&p_pre, g_pre);
    cudaGetSymbolAddress(&p_sq,  g_sqbits);
    cudaGetSymbolAddress(&p_sk,  g_skbits);

    dim3 gg(Dn / 64, Mrows / 64), tb(256);
    gemm256<<<gg, tb>>>(q, wq_k, wq_b, nullptr, (unsigned*)p_sq, nullptr, 1);
    gemm256<<<gg, tb>>>(k, wk_k, wk_b, nullptr, (unsigned*)p_sk, nullptr, 1);
    gemm256<<<gg, tb>>>(v, wv_k, wv_b, nullptr, nullptr, (__half*)p_vph, 2);

    rowsum_kernel<<<dim3((Sn / 64) * 4, Bn), 256>>>();
    attn_mma_kernel<<<dim3(Sn / 64, Bn), 256>>>(mask, attn);

    tanh_anchor_kernel<<<(Mrows * Dn) / 1024, 1024>>>(anchor);
    gemm256<<<gg, tb>>>((const float*)p_pre, dense_k, dense_b, out, nullptr, nullptr, 0);
}

// round 9
// speedup vs baseline: 8.3408x; 1.2803x over previous
#include <cuda_runtime.h>
#include <cuda_fp16.h>
#include <math.h>

#define Bn 4
#define Sn 4096
#define Dn 256
#define Mrows (Bn*Sn)   // 16384

// -------- scratch (device globals; allocation-free rule) --------
__device__ __align__(16) __half   g_vph[(size_t)Mrows * Dn];   // v-projection, fp16
__device__ __align__(16) float    g_pre[(size_t)Mrows * Dn];   // attn^T@vp (raw, pre-tanh)
__device__ __align__(16) unsigned g_sqbits[Mrows * 8];         // sign bits of q-proj
__device__ __align__(16) unsigned g_skbits[Mrows * 8];         // sign bits of k-proj
__device__ __align__(16) float    g_rowsum4[4][Mrows];         // partial softmax denominators
__device__ __align__(16) __half   g_wh[4][Dn * Dn];            // weight hi halves
__device__ __align__(16) __half   g_wl[4][Dn * Dn];            // weight lo halves

__device__ __forceinline__ unsigned s2u(const void* p) {
    return (unsigned)__cvta_generic_to_shared(p);
}

#define LDMX4(r0,r1,r2,r3,addr) \
    asm volatile("ldmatrix.sync.aligned.m8n8.x4.shared.b16 {%0,%1,%2,%3}, [%4];" \
        : "=r"(r0),"=r"(r1),"=r"(r2),"=r"(r3) : "r"(addr))
#define LDMX4T(r0,r1,r2,r3,addr) \
    asm volatile("ldmatrix.sync.aligned.m8n8.x4.trans.shared.b16 {%0,%1,%2,%3}, [%4];" \
        : "=r"(r0),"=r"(r1),"=r"(r2),"=r"(r3) : "r"(addr))
#define MMA16816(C,A0,A1,A2,A3,B0,B1) \
    asm volatile("mma.sync.aligned.m16n8k16.row.col.f32.f16.f16.f32 " \
        "{%0,%1,%2,%3}, {%4,%5,%6,%7}, {%8,%9}, {%0,%1,%2,%3};" \
        : "+f"(C[0]),"+f"(C[1]),"+f"(C[2]),"+f"(C[3]) \
        : "r"(A0),"r"(A1),"r"(A2),"r"(A3), "r"(B0),"r"(B1))

// ============================================================
// Pre-split the 4 weight matrices into hi/lo fp16 halves
// ============================================================
__global__ void wsplit_kernel(const float* __restrict__ w0, const float* __restrict__ w1,
                              const float* __restrict__ w2, const float* __restrict__ w3)
{
    const int idx = blockIdx.x * 256 + threadIdx.x;   // 65536 threads
    const float* ws[4] = {w0, w1, w2, w3};
    #pragma unroll
    for (int m = 0; m < 4; m++) {
        const float x = ws[m][idx];
        const __half h = __float2half_rn(x);
        g_wh[m][idx] = h;
        g_wl[m][idx] = __float2half_rn(x - __half2float(h));
    }
}

// ============================================================
// Tensor-core GEMM: C[M,256] = A[M,256] @ W[256,256] + bias
// split-fp16 (hi*hi + hi*lo + lo*hi), fp32 accumulate.
// CTA = 128m x 128n, 8 warps (4m x 2n), k-step 32.
// mode 0: fp32 out, A pre-processed with tanh(A*anchor)
// mode 1: sign bits out (atomicOr, idempotent)
// mode 2: fp16 out
// ============================================================
#define LDA 40    // A smem pitch (halfs)
#define LDW 136   // W smem pitch (halfs)

__global__ __launch_bounds__(256, 2) void gemm_mma(
    const float* __restrict__ A, int widx,
    const float* __restrict__ bias,
    float* __restrict__ outF, unsigned* __restrict__ outBits,
    __half* __restrict__ outH, const float* __restrict__ anchor, int mode)
{
    __shared__ __align__(16) __half Ah[128][LDA], Al[128][LDA];  // 20480 B
    __shared__ __align__(16) __half Wh[32][LDW], Wl[32][LDW];    // 17408 B

    const int t = threadIdx.x, lane = t & 31, wid = t >> 5;
    const int wm = wid >> 1, wn = wid & 1;
    const int m0 = blockIdx.y * 128, n0 = blockIdx.x * 128;

    float acc[2][8][4];
    #pragma unroll
    for (int m = 0; m < 2; m++)
        #pragma unroll
        for (int n = 0; n < 8; n++)
            #pragma unroll
            for (int j = 0; j < 4; j++) acc[m][n][j] = 0.f;

    const __half* WH = g_wh[widx];
    const __half* WL = g_wl[widx];

    for (int k0 = 0; k0 < Dn; k0 += 32) {
        __syncthreads();   // previous iteration's ldmatrix reads must drain
        // ---- stage A 128x32 fp32 -> hi/lo fp16 (dense mode: tanh(A*anchor)) ----
        #pragma unroll
        for (int i = 0; i < 4; i++) {
            const int u = t + 256 * i, row = u >> 3, c4 = (u & 7) << 2;
            const size_t gidx = (size_t)(m0 + row) * Dn + k0 + c4;
            float4 f = *(const float4*)&A[gidx];
            if (mode == 0) {
                const float4 an = *(const float4*)&anchor[gidx & (size_t)(Sn * Dn - 1)];
                f.x = tanhf(f.x * an.x); f.y = tanhf(f.y * an.y);
                f.z = tanhf(f.z * an.z); f.w = tanhf(f.w * an.w);
            }
            const __half h0 = __float2half_rn(f.x), h1 = __float2half_rn(f.y),
                         h2 = __float2half_rn(f.z), h3 = __float2half_rn(f.w);
            uint2 hi, lo;
            hi.x = (unsigned)__half_as_ushort(h0) | ((unsigned)__half_as_ushort(h1) << 16);
            hi.y = (unsigned)__half_as_ushort(h2) | ((unsigned)__half_as_ushort(h3) << 16);
            const __half l0 = __float2half_rn(f.x - __half2float(h0)),
                         l1 = __float2half_rn(f.y - __half2float(h1)),
                         l2 = __float2half_rn(f.z - __half2float(h2)),
                         l3 = __float2half_rn(f.w - __half2float(h3));
            lo.x = (unsigned)__half_as_ushort(l0) | ((unsigned)__half_as_ushort(l1) << 16);
            lo.y = (unsigned)__half_as_ushort(l2) | ((unsigned)__half_as_ushort(l3) << 16);
            *(uint2*)&Ah[row][c4] = hi;
            *(uint2*)&Al[row][c4] = lo;
        }
        // ---- stage W 32x128 (pre-split halfs, straight copy) ----
        #pragma unroll
        for (int i = 0; i < 2; i++) {
            const int u = t + 256 * i, row = u >> 4, c8 = (u & 15) << 3;
            *(uint4*)&Wh[row][c8] = *(const uint4*)&WH[(size_t)(k0 + row) * Dn + n0 + c8];
            *(uint4*)&Wl[row][c8] = *(const uint4*)&WL[(size_t)(k0 + row) * Dn + n0 + c8];
        }
        __syncthreads();

        // ---- mma: 3 precision combos ----
        const unsigned Ah_b = s2u(&Ah[0][0]), Al_b = s2u(&Al[0][0]);
        const unsigned Wh_b = s2u(&Wh[0][0]), Wl_b = s2u(&Wl[0][0]);
        #pragma unroll
        for (int kt = 0; kt < 2; kt++) {
            unsigned ah0[4], ah1[4], al0[4], al1[4];
            const unsigned arow = (wm * 32 + (lane & 15)) * (LDA * 2)
                                + (kt * 16 + (lane >> 4) * 8) * 2;
            LDMX4(ah0[0], ah0[1], ah0[2], ah0[3], Ah_b + arow);
            LDMX4(ah1[0], ah1[1], ah1[2], ah1[3], Ah_b + arow + 16 * (LDA * 2));
            LDMX4(al0[0], al0[1], al0[2], al0[3], Al_b + arow);
            LDMX4(al1[0], al1[1], al1[2], al1[3], Al_b + arow + 16 * (LDA * 2));
            #pragma unroll
            for (int np = 0; np < 4; np++) {
                unsigned bh[4], bl[4];
                const unsigned baddr = (kt * 16 + (lane & 15)) * (LDW * 2)
                                     + (wn * 64 + np * 16 + (lane >> 4) * 8) * 2;
                LDMX4T(bh[0], bh[1], bh[2], bh[3], Wh_b + baddr);
                LDMX4T(bl[0], bl[1], bl[2], bl[3], Wl_b + baddr);
                // hi*hi
                MMA16816(acc[0][np*2+0], ah0[0],ah0[1],ah0[2],ah0[3], bh[0],bh[1]);
                MMA16816(acc[0][np*2+1], ah0[0],ah0[1],ah0[2],ah0[3], bh[2],bh[3]);
                MMA16816(acc[1][np*2+0], ah1[0],ah1[1],ah1[2],ah1[3], bh[0],bh[1]);
                MMA16816(acc[1][np*2+1], ah1[0],ah1[1],ah1[2],ah1[3], bh[2],bh[3]);
                // hi*lo
                MMA16816(acc[0][np*2+0], ah0[0],ah0[1],ah0[2],ah0[3], bl[0],bl[1]);
                MMA16816(acc[0][np*2+1], ah0[0],ah0[1],ah0[2],ah0[3], bl[2],bl[3]);
                MMA16816(acc[1][np*2+0], ah1[0],ah1[1],ah1[2],ah1[3], bl[0],bl[1]);
                MMA16816(acc[1][np*2+1], ah1[0],ah1[1],ah1[2],ah1[3], bl[2],bl[3]);
                // lo*hi
                MMA16816(acc[0][np*2+0], al0[0],al0[1],al0[2],al0[3], bh[0],bh[1]);
                MMA16816(acc[0][np*2+1], al0[0],al0[1],al0[2],al0[3], bh[2],bh[3]);
                MMA16816(acc[1][np*2+0], al1[0],al1[1],al1[2],al1[3], bh[0],bh[1]);
                MMA16816(acc[1][np*2+1], al1[0],al1[1],al1[2],al1[3], bh[2],bh[3]);
            }
        }
    }

    // ---- epilogue ----
    #pragma unroll
    for (int m = 0; m < 2; m++) {
        #pragma unroll
        for (int j2 = 0; j2 < 2; j2++) {
            const int row = m0 + wm * 32 + m * 16 + (lane >> 2) + j2 * 8;
            unsigned wv[2] = {0u, 0u};
            #pragma unroll
            for (int n = 0; n < 8; n++) {
                const int cl  = wn * 64 + n * 8 + ((lane & 3) << 1);
                const int col = n0 + cl;
                const float2 bv = *(const float2*)&bias[col];
                const float x0 = acc[m][n][j2 * 2 + 0] + bv.x;
                const float x1 = acc[m][n][j2 * 2 + 1] + bv.y;
                if (mode == 0) {
                    *(float2*)&outF[(size_t)row * Dn + col] = make_float2(x0, x1);
                } else if (mode == 2) {
                    unsigned p;
                    asm("cvt.rn.f16x2.f32 %0, %1, %2;" : "=r"(p) : "f"(x1), "f"(x0));
                    *(unsigned*)&outH[(size_t)row * Dn + col] = p;
                } else {
                    const int bit = ((n & 3) * 8) + ((lane & 3) << 1);
                    if (x0 < 0.f) wv[n >> 2] |= 1u << bit;
                    if (x1 < 0.f) wv[n >> 2] |= 1u << (bit + 1);
                }
            }
            if (mode == 1) {
                const int wordb = (n0 + wn * 64) >> 5;
                if (wv[0]) atomicOr(&outBits[row * 8 + wordb + 0], wv[0]);
                if (wv[1]) atomicOr(&outBits[row * 8 + wordb + 1], wv[1]);
            }
        }
    }
}

// ============================================================
// g_rowsum4[qsel][b,k] = sum_{q in qsel-quarter} exp((256-popc)/512)
// ============================================================
__global__ __launch_bounds__(256) void rowsum_kernel()
{
    __shared__ __align__(16) uint4 qbf[1024];      // 512 q-rows * 8 u32
    __shared__ float red[64][4];
    const int t    = threadIdx.x;
    const int b    = blockIdx.y;
    const int k0   = (blockIdx.x >> 2) * 64;
    const int qsel = blockIdx.x & 3;

    const int kr = t >> 2, part = t & 3;
    const uint4* kb = (const uint4*)&g_skbits[((size_t)b * Sn + k0 + kr) * 8];
    const uint4 k0v = kb[0], k1v = kb[1];
    float sum = 0.f;

    for (int q0 = qsel * 1024; q0 < qsel * 1024 + 1024; q0 += 512) {
        const uint4* src = (const uint4*)&g_sqbits[((size_t)b * Sn + q0) * 8];
        __syncthreads();
        #pragma unroll
        for (int i = 0; i < 4; i++) qbf[t + 256 * i] = src[t + 256 * i];
        __syncthreads();
        for (int q = part; q < 512; q += 4) {
            uint4 a = qbf[q * 2], c = qbf[q * 2 + 1];
            int pc = __popc(a.x ^ k0v.x) + __popc(a.y ^ k0v.y)
                   + __popc(a.z ^ k0v.z) + __popc(a.w ^ k0v.w)
                   + __popc(c.x ^ k1v.x) + __popc(c.y ^ k1v.y)
                   + __popc(c.z ^ k1v.z) + __popc(c.w ^ k1v.w);
            sum += __expf((float)(256 - pc) * (1.0f / 512.0f));
        }
    }
    red[kr][part] = sum;
    __syncthreads();
    if (t < 64)
        g_rowsum4[qsel][(size_t)b * Sn + k0 + t] =
            (red[t][0] + red[t][1]) + (red[t][2] + red[t][3]);
}

// ============================================================
// Fused: attn[b,k,q] (fp32 -> d_out) + g_pre[b,q,d] via mma.sync fp16
// ============================================================
#define LDD 264   // vp_s row pitch in halfs (256 + 8)
#define LDK 40    // ats  row pitch in halfs (32 + 8)

__global__ __launch_bounds__(256, 2) void attn_mma_kernel(
    const float* __restrict__ mask, float* __restrict__ attn_out)
{
    __shared__ __align__(16) __half   vp_s[2][32][LDD];  // 33792 B
    __shared__ __align__(16) __half   ats[64][LDK];      //  5120 B
    __shared__ __align__(16) float    msk[32][64];       //  8192 B
    __shared__ __align__(16) unsigned skb[32][8];        //  1024 B
    __shared__ float inv_rs[32];

    const int t    = threadIdx.x;
    const int b    = blockIdx.y;
    const int q0   = blockIdx.x * 64;
    const int lane = t & 31, wid = t >> 5;
    const int wq   = wid >> 2, wd = wid & 3;
    const int qq   = t & 63;

    const uint4* sqp = (const uint4*)&g_sqbits[((size_t)b * Sn + q0 + qq) * 8];
    const uint4 sq0 = sqp[0], sq1 = sqp[1];

    float acc[2][8][4];
    #pragma unroll
    for (int m = 0; m < 2; m++)
        #pragma unroll
        for (int n = 0; n < 8; n++)
            #pragma unroll
            for (int j = 0; j < 4; j++) acc[m][n][j] = 0.f;

    uint4  vpr[4];
    float4 mkr[2];
    uint4  skr;
    float  invr = 0.f;

    {
        const uint4* vg = (const uint4*)&g_vph[((size_t)b * Sn) * Dn];
        #pragma unroll
        for (int i = 0; i < 4; i++) vpr[i] = vg[t + 256 * i];
        #pragma unroll
        for (int i = 0; i < 2; i++) {
            const int u = t + 256 * i, kk = u >> 4, q4 = (u & 15) << 2;
            mkr[i] = *(const float4*)&mask[((size_t)b * Sn + kk) * Sn + q0 + q4];
        }
        if (t < 64) skr = ((const uint4*)&g_skbits[((size_t)b * Sn) * 8])[t];
        if (t < 32) {
            const size_t r = (size_t)b * Sn + t;
            invr = 1.0f / (g_rowsum4[0][r] + g_rowsum4[1][r] + g_rowsum4[2][r] + g_rowsum4[3][r]);
        }
    }

    const unsigned ats_base = s2u(&ats[0][0]);

    for (int it = 0; it < Sn / 32; it++) {
        const int cur = it & 1;
        #pragma unroll
        for (int i = 0; i < 4; i++) {
            const int u = t + 256 * i;
            *(uint4*)&vp_s[cur][u >> 5][(u & 31) << 3] = vpr[i];
        }
        #pragma unroll
        for (int i = 0; i < 2; i++) {
            const int u = t + 256 * i;
            *(float4*)&msk[u >> 4][(u & 15) << 2] = mkr[i];
        }
        if (t < 64) ((uint4*)skb)[t] = skr;
        if (t < 32) inv_rs[t] = invr;

        if (it + 1 < Sn / 32) {
            const int k0n = (it + 1) * 32;
            const uint4* vg = (const uint4*)&g_vph[((size_t)b * Sn + k0n) * Dn];
            #pragma unroll
            for (int i = 0; i < 4; i++) vpr[i] = vg[t + 256 * i];
            #pragma unroll
            for (int i = 0; i < 2; i++) {
                const int u = t + 256 * i, kk = u >> 4, q4 = (u & 15) << 2;
                mkr[i] = *(const float4*)&mask[((size_t)b * Sn + k0n + kk) * Sn + q0 + q4];
            }
            if (t < 64) skr = ((const uint4*)&g_skbits[((size_t)b * Sn + k0n) * 8])[t];
            if (t < 32) {
                const size_t r = (size_t)b * Sn + k0n + t;
                invr = 1.0f / (g_rowsum4[0][r] + g_rowsum4[1][r] + g_rowsum4[2][r] + g_rowsum4[3][r]);
            }
        }
        __syncthreads();

        #pragma unroll
        for (int r = 0; r < 4; r++) {
            const int kk = ((t >> 6) << 1) + (r << 3);
            float a2[2];
            #pragma unroll
            for (int j = 0; j < 2; j++) {
                const unsigned* sk = skb[kk + j];
                int pc = __popc(sk[0] ^ sq0.x) + __popc(sk[1] ^ sq0.y)
                       + __popc(sk[2] ^ sq0.z) + __popc(sk[3] ^ sq0.w)
                       + __popc(sk[4] ^ sq1.x) + __popc(sk[5] ^ sq1.y)
                       + __popc(sk[6] ^ sq1.z) + __popc(sk[7] ^ sq1.w);
                const float a = __expf((float)(256 - pc) * (1.0f / 512.0f))
                              * inv_rs[kk + j] * msk[kk + j][qq];
                a2[j] = a;
                attn_out[((size_t)b * Sn + it * 32 + kk + j) * Sn + q0 + qq] = a;
            }
            unsigned p;
            asm("cvt.rn.f16x2.f32 %0, %1, %2;" : "=r"(p) : "f"(a2[1]), "f"(a2[0]));
            *(unsigned*)&ats[qq][kk] = p;
        }
        __syncthreads();

        const unsigned vp_base = s2u(&vp_s[cur][0][0]);
        #pragma unroll
        for (int kt = 0; kt < 2; kt++) {
            unsigned a0[4], a1[4];
            const unsigned acol = (kt * 16 + (lane >> 4) * 8) * 2;
            LDMX4(a0[0], a0[1], a0[2], a0[3],
                  ats_base + (wq * 32 + (lane & 15)) * (LDK * 2) + acol);
            LDMX4(a1[0], a1[1], a1[2], a1[3],
                  ats_base + (wq * 32 + 16 + (lane & 15)) * (LDK * 2) + acol);
            #pragma unroll
            for (int np = 0; np < 4; np++) {
                unsigned bf[4];
                LDMX4T(bf[0], bf[1], bf[2], bf[3],
                       vp_base + (kt * 16 + (lane & 15)) * (LDD * 2)
                               + (wd * 64 + np * 16 + (lane >> 4) * 8) * 2);
                MMA16816(acc[0][np * 2 + 0], a0[0], a0[1], a0[2], a0[3], bf[0], bf[1]);
                MMA16816(acc[0][np * 2 + 1], a0[0], a0[1], a0[2], a0[3], bf[2], bf[3]);
                MMA16816(acc[1][np * 2 + 0], a1[0], a1[1], a1[2], a1[3], bf[0], bf[1]);
                MMA16816(acc[1][np * 2 + 1], a1[0], a1[1], a1[2], a1[3], bf[2], bf[3]);
            }
        }
    }

    #pragma unroll
    for (int m = 0; m < 2; m++) {
        const int q = q0 + wq * 32 + m * 16 + (lane >> 2);
        #pragma unroll
        for (int n = 0; n < 8; n++) {
            const int d = wd * 64 + n * 8 + ((lane & 3) << 1);
            *(float2*)&g_pre[((size_t)b * Sn + q) * Dn + d] =
                make_float2(acc[m][n][0], acc[m][n][1]);
            *(float2*)&g_pre[((size_t)b * Sn + q + 8) * Dn + d] =
                make_float2(acc[m][n][2], acc[m][n][3]);
        }
    }
}

// ============================================================
extern "C" void kernel_launch(void* const* d_in, const int* in_sizes, int n_in,
                              void* d_out, int out_size)
{
    const float* v       = (const float*)d_in[0];
    const float* k       = (const float*)d_in[1];
    const float* q       = (const float*)d_in[2];
    const float* mask    = (const float*)d_in[3];
    const float* wq_k    = (const float*)d_in[4];
    const float* wq_b    = (const float*)d_in[5];
    const float* wk_k    = (const float*)d_in[6];
    const float* wk_b    = (const float*)d_in[7];
    const float* wv_k    = (const float*)d_in[8];
    const float* wv_b    = (const float*)d_in[9];
    const float* anchor  = (const float*)d_in[10];
    const float* dense_k = (const float*)d_in[11];
    const float* dense_b = (const float*)d_in[12];

    float* out  = (float*)d_out;                      // [B,S,D]
    float* attn = out + (size_t)Mrows * Dn;           // [B,S,S]

    void *p_vph, *p_pre, *p_sq, *p_sk;
    cudaGetSymbolAddress(&p_vph, g_vph);
    cudaGetSymbolAddress(&p_pre, g_pre);
    cudaGetSymbolAddress(&p_sq,  g_sqbits);
    cudaGetSymbolAddress(&p_sk,  g_skbits);

    wsplit_kernel<<<256, 256>>>(wq_k, wk_k, wv_k, dense_k);

    dim3 gg(Dn / 128, Mrows / 128), tb(256);   // (2, 128)
    gemm_mma<<<gg, tb>>>(q, 0, wq_b, nullptr, (unsigned*)p_sq, nullptr, nullptr, 1);
    gemm_mma<<<gg, tb>>>(k, 1, wk_b, nullptr, (unsigned*)p_sk, nullptr, nullptr, 1);
    gemm_mma<<<gg, tb>>>(v, 2, wv_b, nullptr, nullptr, (__half*)p_vph, nullptr, 2);

    rowsum_kernel<<<dim3((Sn / 64) * 4, Bn), 256>>>();
    attn_mma_kernel<<<dim3(Sn / 64, Bn), 256>>>(mask, attn);

    gemm_mma<<<gg, tb>>>((const float*)p_pre, 3, dense_b, out, nullptr, nullptr, anchor, 0);
}

// round 14
// speedup vs baseline: 8.3553x; 1.0017x over previous
#include <cuda_runtime.h>
#include <cuda_fp16.h>
#include <math.h>

#define Bn 4
#define Sn 4096
#define Dn 256
#define Mrows (Bn*Sn)   // 16384
#define NIT  (Sn/32)    // 128

// -------- scratch (device globals; allocation-free rule) --------
__device__ __align__(16) __half   g_vph[(size_t)Mrows * Dn];
__device__ __align__(16) float    g_pre[(size_t)Mrows * Dn];
__device__ __align__(16) unsigned g_sqbits[Mrows * 8];
__device__ __align__(16) unsigned g_skbits[Mrows * 8];
__device__ __align__(16) float    g_rowsum4[4][Mrows];
__device__ __align__(16) __half   g_wh[4][Dn * Dn];
__device__ __align__(16) __half   g_wl[4][Dn * Dn];

__device__ __forceinline__ unsigned s2u(const void* p) {
    return (unsigned)__cvta_generic_to_shared(p);
}

#define LDMX4(r0,r1,r2,r3,addr) \
    asm volatile("ldmatrix.sync.aligned.m8n8.x4.shared.b16 {%0,%1,%2,%3}, [%4];" \
        : "=r"(r0),"=r"(r1),"=r"(r2),"=r"(r3) : "r"(addr))
#define LDMX4T(r0,r1,r2,r3,addr) \
    asm volatile("ldmatrix.sync.aligned.m8n8.x4.trans.shared.b16 {%0,%1,%2,%3}, [%4];" \
        : "=r"(r0),"=r"(r1),"=r"(r2),"=r"(r3) : "r"(addr))
#define MMA16816(C,A0,A1,A2,A3,B0,B1) \
    asm volatile("mma.sync.aligned.m16n8k16.row.col.f32.f16.f16.f32 " \
        "{%0,%1,%2,%3}, {%4,%5,%6,%7}, {%8,%9}, {%0,%1,%2,%3};" \
        : "+f"(C[0]),"+f"(C[1]),"+f"(C[2]),"+f"(C[3]) \
        : "r"(A0),"r"(A1),"r"(A2),"r"(A3), "r"(B0),"r"(B1))

// ============================================================
// Pre-split the 4 weight matrices into hi/lo fp16 halves
// ============================================================
__global__ void wsplit_kernel(const float* __restrict__ w0, const float* __restrict__ w1,
                              const float* __restrict__ w2, const float* __restrict__ w3)
{
    const int idx = blockIdx.x * 256 + threadIdx.x;
    const float* ws[4] = {w0, w1, w2, w3};
    #pragma unroll
    for (int m = 0; m < 4; m++) {
        const float x = ws[m][idx];
        const __half h = __float2half_rn(x);
        g_wh[m][idx] = h;
        g_wl[m][idx] = __float2half_rn(x - __half2float(h));
    }
}

// ============================================================
// shared GEMM mainloop pieces (split-fp16, m16n8k16)
// CTA = 128m x 128n, 8 warps (4m x 2n), k-step 32.
// ============================================================
#define LDA 40    // A smem pitch (halfs)
#define LDW 136   // W smem pitch (halfs)

#define GEMM_STAGE_A(A, DO_TANH) \
    _Pragma("unroll") \
    for (int i = 0; i < 4; i++) { \
        const int u = t + 256 * i, row = u >> 3, c4 = (u & 7) << 2; \
        const size_t gidx = (size_t)(m0 + row) * Dn + k0 + c4; \
        float4 f = *(const float4*)&(A)[gidx]; \
        if (DO_TANH) { \
            const float4 an = *(const float4*)&anchor[gidx & (size_t)(Sn * Dn - 1)]; \
            f.x = tanhf(f.x * an.x); f.y = tanhf(f.y * an.y); \
            f.z = tanhf(f.z * an.z); f.w = tanhf(f.w * an.w); \
        } \
        const __half h0 = __float2half_rn(f.x), h1 = __float2half_rn(f.y), \
                     h2 = __float2half_rn(f.z), h3 = __float2half_rn(f.w); \
        uint2 hi, lo; \
        hi.x = (unsigned)__half_as_ushort(h0) | ((unsigned)__half_as_ushort(h1) << 16); \
        hi.y = (unsigned)__half_as_ushort(h2) | ((unsigned)__half_as_ushort(h3) << 16); \
        const __half l0 = __float2half_rn(f.x - __half2float(h0)), \
                     l1 = __float2half_rn(f.y - __half2float(h1)), \
                     l2 = __float2half_rn(f.z - __half2float(h2)), \
                     l3 = __float2half_rn(f.w - __half2float(h3)); \
        lo.x = (unsigned)__half_as_ushort(l0) | ((unsigned)__half_as_ushort(l1) << 16); \
        lo.y = (unsigned)__half_as_ushort(l2) | ((unsigned)__half_as_ushort(l3) << 16); \
        *(uint2*)&Ah[row][c4] = hi; \
        *(uint2*)&Al[row][c4] = lo; \
    }

#define GEMM_STAGE_W(WH, WL) \
    _Pragma("unroll") \
    for (int i = 0; i < 2; i++) { \
        const int u = t + 256 * i, row = u >> 4, c8 = (u & 15) << 3; \
        *(uint4*)&Wh[row][c8] = *(const uint4*)&(WH)[(size_t)(k0 + row) * Dn + n0 + c8]; \
        *(uint4*)&Wl[row][c8] = *(const uint4*)&(WL)[(size_t)(k0 + row) * Dn + n0 + c8]; \
    }

#define GEMM_MMA_BODY() { \
    const unsigned Ah_b = s2u(&Ah[0][0]), Al_b = s2u(&Al[0][0]); \
    const unsigned Wh_b = s2u(&Wh[0][0]), Wl_b = s2u(&Wl[0][0]); \
    _Pragma("unroll") \
    for (int kt = 0; kt < 2; kt++) { \
        unsigned ah0[4], ah1[4], al0[4], al1[4]; \
        const unsigned arow = (wm * 32 + (lane & 15)) * (LDA * 2) \
                            + (kt * 16 + (lane >> 4) * 8) * 2; \
        LDMX4(ah0[0], ah0[1], ah0[2], ah0[3], Ah_b + arow); \
        LDMX4(ah1[0], ah1[1], ah1[2], ah1[3], Ah_b + arow + 16 * (LDA * 2)); \
        LDMX4(al0[0], al0[1], al0[2], al0[3], Al_b + arow); \
        LDMX4(al1[0], al1[1], al1[2], al1[3], Al_b + arow + 16 * (LDA * 2)); \
        _Pragma("unroll") \
        for (int np = 0; np < 4; np++) { \
            unsigned bh[4], bl[4]; \
            const unsigned baddr = (kt * 16 + (lane & 15)) * (LDW * 2) \
                                 + (wn * 64 + np * 16 + (lane >> 4) * 8) * 2; \
            LDMX4T(bh[0], bh[1], bh[2], bh[3], Wh_b + baddr); \
            LDMX4T(bl[0], bl[1], bl[2], bl[3], Wl_b + baddr); \
            MMA16816(acc[0][np*2+0], ah0[0],ah0[1],ah0[2],ah0[3], bh[0],bh[1]); \
            MMA16816(acc[0][np*2+1], ah0[0],ah0[1],ah0[2],ah0[3], bh[2],bh[3]); \
            MMA16816(acc[1][np*2+0], ah1[0],ah1[1],ah1[2],ah1[3], bh[0],bh[1]); \
            MMA16816(acc[1][np*2+1], ah1[0],ah1[1],ah1[2],ah1[3], bh[2],bh[3]); \
            MMA16816(acc[0][np*2+0], ah0[0],ah0[1],ah0[2],ah0[3], bl[0],bl[1]); \
            MMA16816(acc[0][np*2+1], ah0[0],ah0[1],ah0[2],ah0[3], bl[2],bl[3]); \
            MMA16816(acc[1][np*2+0], ah1[0],ah1[1],ah1[2],ah1[3], bl[0],bl[1]); \
            MMA16816(acc[1][np*2+1], ah1[0],ah1[1],ah1[2],ah1[3], bl[2],bl[3]); \
            MMA16816(acc[0][np*2+0], al0[0],al0[1],al0[2],al0[3], bh[0],bh[1]); \
            MMA16816(acc[0][np*2+1], al0[0],al0[1],al0[2],al0[3], bh[2],bh[3]); \
            MMA16816(acc[1][np*2+0], al1[0],al1[1],al1[2],al1[3], bh[0],bh[1]); \
            MMA16816(acc[1][np*2+1], al1[0],al1[1],al1[2],al1[3], bh[2],bh[3]); \
        } \
    } }

// ---- q/k/v projections, merged: blockIdx.z selects which ----
__global__ __launch_bounds__(256, 2) void proj_mma(
    const float* __restrict__ Aq, const float* __restrict__ Ak, const float* __restrict__ Av,
    const float* __restrict__ bq, const float* __restrict__ bk, const float* __restrict__ bv,
    unsigned* __restrict__ oSq, unsigned* __restrict__ oSk, __half* __restrict__ oVh)
{
    __shared__ __align__(16) __half Ah[128][LDA], Al[128][LDA];
    __shared__ __align__(16) __half Wh[32][LDW], Wl[32][LDW];

    const int t = threadIdx.x, lane = t & 31, wid = t >> 5;
    const int wm = wid >> 1, wn = wid & 1;
    const int m0 = blockIdx.y * 128, n0 = blockIdx.x * 128;
    const int z  = blockIdx.z;
    const float* anchor = nullptr;   // referenced (dead) by GEMM_STAGE_A(A, false)

    const float* A    = (z == 0) ? Aq : (z == 1) ? Ak : Av;
    const float* bias = (z == 0) ? bq : (z == 1) ? bk : bv;
    unsigned* outBits = (z == 0) ? oSq : oSk;
    const __half* WH = g_wh[z];
    const __half* WL = g_wl[z];

    float acc[2][8][4];
    #pragma unroll
    for (int m = 0; m < 2; m++)
        #pragma unroll
        for (int n = 0; n < 8; n++)
            #pragma unroll
            for (int j = 0; j < 4; j++) acc[m][n][j] = 0.f;

    for (int k0 = 0; k0 < Dn; k0 += 32) {
        __syncthreads();
        GEMM_STAGE_A(A, false)
        GEMM_STAGE_W(WH, WL)
        __syncthreads();
        GEMM_MMA_BODY()
    }

    #pragma unroll
    for (int m = 0; m < 2; m++) {
        #pragma unroll
        for (int j2 = 0; j2 < 2; j2++) {
            const int row = m0 + wm * 32 + m * 16 + (lane >> 2) + j2 * 8;
            unsigned wv[2] = {0u, 0u};
            #pragma unroll
            for (int n = 0; n < 8; n++) {
                const int cl  = wn * 64 + n * 8 + ((lane & 3) << 1);
                const int col = n0 + cl;
                const float2 bv2 = *(const float2*)&bias[col];
                const float x0 = acc[m][n][j2 * 2 + 0] + bv2.x;
                const float x1 = acc[m][n][j2 * 2 + 1] + bv2.y;
                if (z == 2) {
                    unsigned p;
                    asm("cvt.rn.f16x2.f32 %0, %1, %2;" : "=r"(p) : "f"(x1), "f"(x0));
                    *(unsigned*)&oVh[(size_t)row * Dn + col] = p;
                } else {
                    const int bit = ((n & 3) * 8) + ((lane & 3) << 1);
                    if (x0 < 0.f) wv[n >> 2] |= 1u << bit;
                    if (x1 < 0.f) wv[n >> 2] |= 1u << (bit + 1);
                }
            }
            if (z != 2) {
                const int wordb = (n0 + wn * 64) >> 5;
                if (wv[0]) atomicOr(&outBits[row * 8 + wordb + 0], wv[0]);
                if (wv[1]) atomicOr(&outBits[row * 8 + wordb + 1], wv[1]);
            }
        }
    }
}

// ---- dense: out = tanh(g_pre*anchor) @ dense_k + dense_b ----
__global__ __launch_bounds__(256, 2) void dense_mma(
    const float* __restrict__ A, const float* __restrict__ bias,
    float* __restrict__ outF, const float* __restrict__ anchor)
{
    __shared__ __align__(16) __half Ah[128][LDA], Al[128][LDA];
    __shared__ __align__(16) __half Wh[32][LDW], Wl[32][LDW];

    const int t = threadIdx.x, lane = t & 31, wid = t >> 5;
    const int wm = wid >> 1, wn = wid & 1;
    const int m0 = blockIdx.y * 128, n0 = blockIdx.x * 128;

    const __half* WH = g_wh[3];
    const __half* WL = g_wl[3];

    float acc[2][8][4];
    #pragma unroll
    for (int m = 0; m < 2; m++)
        #pragma unroll
        for (int n = 0; n < 8; n++)
            #pragma unroll
            for (int j = 0; j < 4; j++) acc[m][n][j] = 0.f;

    for (int k0 = 0; k0 < Dn; k0 += 32) {
        __syncthreads();
        GEMM_STAGE_A(A, true)
        GEMM_STAGE_W(WH, WL)
        __syncthreads();
        GEMM_MMA_BODY()
    }

    #pragma unroll
    for (int m = 0; m < 2; m++) {
        #pragma unroll
        for (int j2 = 0; j2 < 2; j2++) {
            const int row = m0 + wm * 32 + m * 16 + (lane >> 2) + j2 * 8;
            #pragma unroll
            for (int n = 0; n < 8; n++) {
                const int col = n0 + wn * 64 + n * 8 + ((lane & 3) << 1);
                const float2 bv2 = *(const float2*)&bias[col];
                *(float2*)&outF[(size_t)row * Dn + col] =
                    make_float2(acc[m][n][j2*2+0] + bv2.x, acc[m][n][j2*2+1] + bv2.y);
            }
        }
    }
}

// ============================================================
// g_rowsum4[qsel][b,k] = sum_{q in quarter} exp((256-popc)/512)
// ============================================================
__global__ __launch_bounds__(256) void rowsum_kernel()
{
    __shared__ __align__(16) uint4 qbf[1024];
    __shared__ float red[64][4];
    const int t    = threadIdx.x;
    const int b    = blockIdx.y;
    const int k0   = (blockIdx.x >> 2) * 64;
    const int qsel = blockIdx.x & 3;

    const int kr = t >> 2, part = t & 3;
    const uint4* kb = (const uint4*)&g_skbits[((size_t)b * Sn + k0 + kr) * 8];
    const uint4 k0v = kb[0], k1v = kb[1];
    float sum = 0.f;

    for (int q0 = qsel * 1024; q0 < qsel * 1024 + 1024; q0 += 512) {
        const uint4* src = (const uint4*)&g_sqbits[((size_t)b * Sn + q0) * 8];
        __syncthreads();
        #pragma unroll
        for (int i = 0; i < 4; i++) qbf[t + 256 * i] = src[t + 256 * i];
        __syncthreads();
        for (int q = part; q < 512; q += 4) {
            uint4 a = qbf[q * 2], c = qbf[q * 2 + 1];
            int pc = __popc(a.x ^ k0v.x) + __popc(a.y ^ k0v.y)
                   + __popc(a.z ^ k0v.z) + __popc(a.w ^ k0v.w)
                   + __popc(c.x ^ k1v.x) + __popc(c.y ^ k1v.y)
                   + __popc(c.z ^ k1v.z) + __popc(c.w ^ k1v.w);
            sum += __expf((float)(256 - pc) * (1.0f / 512.0f));
        }
    }
    red[kr][part] = sum;
    __syncthreads();
    if (t < 64)
        g_rowsum4[qsel][(size_t)b * Sn + k0 + t] =
            (red[t][0] + red[t][1]) + (red[t][2] + red[t][3]);
}

// ============================================================
// Fused attn + AV mma, single-barrier pipeline.
// Interval it: MMA(tile it) | popc->ats(tile it+1) | stage vp(it+1),
// skb/inv(it+2) | LDG vp(it+2), skb/inv(it+3), mask(it+2).
// ============================================================
#define LDD 264
#define LDK 40

__global__ __launch_bounds__(256, 2) void attn_mma_kernel(
    const float* __restrict__ mask, float* __restrict__ attn_out)
{
    __shared__ __align__(16) __half   vp_s[2][32][LDD];  // 33792 B
    __shared__ __align__(16) __half   ats[2][64][LDK];   // 10240 B
    __shared__ __align__(16) unsigned skb[2][32][8];     //  2048 B
    __shared__ float inv_rs[2][32];                      //   256 B  (46336 total)

    const int t    = threadIdx.x;
    const int b    = blockIdx.y;
    const int q0   = blockIdx.x * 64;
    const int lane = t & 31, wid = t >> 5;
    const int wq   = wid >> 2, wd = wid & 3;
    const int qq   = t & 63, g = t >> 6;
    const size_t bS = (size_t)b * Sn;

    const uint4* sqp = (const uint4*)&g_sqbits[(bS + q0 + qq) * 8];
    const uint4 sq0 = sqp[0], sq1 = sqp[1];

    float acc[2][8][4];
    #pragma unroll
    for (int m = 0; m < 2; m++)
        #pragma unroll
        for (int n = 0; n < 8; n++)
            #pragma unroll
            for (int j = 0; j < 4; j++) acc[m][n][j] = 0.f;

    uint4 vpr[4]; uint4 skr; float invr = 0.f;
    float mrg0[8], mrg1[8];

#define A_LDG_VP(TILE) { \
    const uint4* vg = (const uint4*)&g_vph[(bS + (TILE) * 32) * Dn]; \
    _Pragma("unroll") for (int i = 0; i < 4; i++) vpr[i] = vg[t + 256 * i]; }
#define A_STS_VP(BUF) { \
    _Pragma("unroll") for (int i = 0; i < 4; i++) { \
        const int u = t + 256 * i; \
        *(uint4*)&vp_s[BUF][u >> 5][(u & 31) << 3] = vpr[i]; } }
#define A_LDG_SKIN(TILE) { \
    if (t < 64) skr = ((const uint4*)&g_skbits[(bS + (TILE) * 32) * 8])[t]; \
    if (t < 32) { const size_t r = bS + (TILE) * 32 + t; \
        invr = 1.0f / (g_rowsum4[0][r] + g_rowsum4[1][r] + g_rowsum4[2][r] + g_rowsum4[3][r]); } }
#define A_STS_SKIN(BUF) { \
    if (t < 64) ((uint4*)skb[BUF])[t] = skr; \
    if (t < 32) inv_rs[BUF][t] = invr; }
#define A_LDG_MASK(TILE, MRG) { \
    _Pragma("unroll") for (int r = 0; r < 4; r++) { \
        _Pragma("unroll") for (int j = 0; j < 2; j++) { \
            const int kk = 2 * g + (r << 3) + j; \
            MRG[r * 2 + j] = mask[(bS + (TILE) * 32 + kk) * Sn + q0 + qq]; } } }
#define A_POPC(TILE, BUF, MRG) { \
    _Pragma("unroll") for (int r = 0; r < 4; r++) { \
        const int kk = 2 * g + (r << 3); \
        float a2[2]; \
        _Pragma("unroll") for (int j = 0; j < 2; j++) { \
            const unsigned* sk = skb[BUF][kk + j]; \
            int pc = __popc(sk[0] ^ sq0.x) + __popc(sk[1] ^ sq0.y) \
                   + __popc(sk[2] ^ sq0.z) + __popc(sk[3] ^ sq0.w) \
                   + __popc(sk[4] ^ sq1.x) + __popc(sk[5] ^ sq1.y) \
                   + __popc(sk[6] ^ sq1.z) + __popc(sk[7] ^ sq1.w); \
            const float a = __expf((float)(256 - pc) * (1.0f / 512.0f)) \
                          * inv_rs[BUF][kk + j] * MRG[r * 2 + j]; \
            a2[j] = a; \
            attn_out[(bS + (TILE) * 32 + kk + j) * Sn + q0 + qq] = a; } \
        unsigned p; \
        asm("cvt.rn.f16x2.f32 %0, %1, %2;" : "=r"(p) : "f"(a2[1]), "f"(a2[0])); \
        *(unsigned*)&ats[BUF][qq][kk] = p; } }
#define A_MMA(BUF) { \
    const unsigned ats_b = s2u(&ats[BUF][0][0]); \
    const unsigned vp_b  = s2u(&vp_s[BUF][0][0]); \
    _Pragma("unroll") for (int kt = 0; kt < 2; kt++) { \
        unsigned a0[4], a1[4]; \
        const unsigned acol = (kt * 16 + (lane >> 4) * 8) * 2; \
        LDMX4(a0[0], a0[1], a0[2], a0[3], \
              ats_b + (wq * 32 + (lane & 15)) * (LDK * 2) + acol); \
        LDMX4(a1[0], a1[1], a1[2], a1[3], \
              ats_b + (wq * 32 + 16 + (lane & 15)) * (LDK * 2) + acol); \
        _Pragma("unroll") for (int np = 0; np < 4; np++) { \
            unsigned bf[4]; \
            LDMX4T(bf[0], bf[1], bf[2], bf[3], \
                   vp_b + (kt * 16 + (lane & 15)) * (LDD * 2) \
                        + (wd * 64 + np * 16 + (lane >> 4) * 8) * 2); \
            MMA16816(acc[0][np * 2 + 0], a0[0], a0[1], a0[2], a0[3], bf[0], bf[1]); \
            MMA16816(acc[0][np * 2 + 1], a0[0], a0[1], a0[2], a0[3], bf[2], bf[3]); \
            MMA16816(acc[1][np * 2 + 0], a1[0], a1[1], a1[2], a1[3], bf[0], bf[1]); \
            MMA16816(acc[1][np * 2 + 1], a1[0], a1[1], a1[2], a1[3], bf[2], bf[3]); } } }
// Interval: CUR = it&1, NXT = !CUR. MRGNXT = mask regs for tile it+1 (consumed),
// MRGCUR = set being refilled for tile it+2.
#define A_INTERVAL(IT, CUR, NXT, MRGNXT, MRGCUR) { \
    A_STS_VP(NXT) \
    if ((IT) + 2 < NIT) { A_STS_SKIN(CUR) } \
    if ((IT) + 2 < NIT) { A_LDG_VP((IT) + 2) } \
    if ((IT) + 3 < NIT) { A_LDG_SKIN((IT) + 3) } \
    if ((IT) + 2 < NIT) { A_LDG_MASK((IT) + 2, MRGCUR) } \
    A_MMA(CUR) \
    A_POPC((IT) + 1, NXT, MRGNXT) \
    __syncthreads(); }

    // ---- prologue ----
    A_LDG_VP(0)  A_LDG_SKIN(0)  A_LDG_MASK(0, mrg0)
    A_STS_VP(0)  A_STS_SKIN(0)
    A_LDG_VP(1)  A_LDG_SKIN(1)  A_LDG_MASK(1, mrg1)
    __syncthreads();                 // vp[0], skb[0], inv[0] visible
    A_POPC(0, 0, mrg0)               // writes ats[0]
    A_STS_SKIN(1)                    // skb[1], inv[1]
    A_LDG_SKIN(2)                    // regs for STS in interval 0
    __syncthreads();                 // enter interval 0

    // ---- main pipeline: intervals 0..126 ----
    for (int it = 0; it < NIT - 2; it += 2) {
        A_INTERVAL(it,     0, 1, mrg1, mrg0)
        A_INTERVAL(it + 1, 1, 0, mrg0, mrg1)
    }
    A_INTERVAL(NIT - 2, 0, 1, mrg1, mrg0)   // interval 126
    A_MMA(1)                                 // tile 127

    // ---- epilogue: fragments -> g_pre ----
    #pragma unroll
    for (int m = 0; m < 2; m++) {
        const int q = q0 + wq * 32 + m * 16 + (lane >> 2);
        #pragma unroll
        for (int n = 0; n < 8; n++) {
            const int d = wd * 64 + n * 8 + ((lane & 3) << 1);
            *(float2*)&g_pre[(bS + q) * Dn + d] =
                make_float2(acc[m][n][0], acc[m][n][1]);
            *(float2*)&g_pre[(bS + q + 8) * Dn + d] =
                make_float2(acc[m][n][2], acc[m][n][3]);
        }
    }
}

// ============================================================
extern "C" void kernel_launch(void* const* d_in, const int* in_sizes, int n_in,
                              void* d_out, int out_size)
{
    const float* v       = (const float*)d_in[0];
    const float* k       = (const float*)d_in[1];
    const float* q       = (const float*)d_in[2];
    const float* mask    = (const float*)d_in[3];
    const float* wq_k    = (const float*)d_in[4];
    const float* wq_b    = (const float*)d_in[5];
    const float* wk_k    = (const float*)d_in[6];
    const float* wk_b    = (const float*)d_in[7];
    const float* wv_k    = (const float*)d_in[8];
    const float* wv_b    = (const float*)d_in[9];
    const float* anchor  = (const float*)d_in[10];
    const float* dense_k = (const float*)d_in[11];
    const float* dense_b = (const float*)d_in[12];

    float* out  = (float*)d_out;                      // [B,S,D]
    float* attn = out + (size_t)Mrows * Dn;           // [B,S,S]

    void *p_vph, *p_pre, *p_sq, *p_sk;
    cudaGetSymbolAddress(&p_vph, g_vph);
    cudaGetSymbolAddress(&p_pre, g_pre);
    cudaGetSymbolAddress(&p_sq,  g_sqbits);
    cudaGetSymbolAddress(&p_sk,  g_skbits);

    wsplit_kernel<<<256, 256>>>(wq_k, wk_k, wv_k, dense_k);

    proj_mma<<<dim3(Dn / 128, Mrows / 128, 3), 256>>>(
        q, k, v, wq_b, wk_b, wv_b,
        (unsigned*)p_sq, (unsigned*)p_sk, (__half*)p_vph);

    rowsum_kernel<<<dim3((Sn / 64) * 4, Bn), 256>>>();
    attn_mma_kernel<<<dim3(Sn / 64, Bn), 256>>>(mask, attn);

    dense_mma<<<dim3(Dn / 128, Mrows / 128), 256>>>(
        (const float*)p_pre, dense_b, out, anchor);
}